// round 16
// baseline (speedup 1.0000x reference)
#include <cuda_runtime.h>
#include <cuda_fp16.h>
#include <math.h>
#include <stdint.h>

#define LSEQ 1024
#define BATCH 8
#define HDIM 300
#define NC 11234
#define W1COLS 650
#define NPAIR (BATCH * NC)
#define KPAD 320

// ---------------- device scratch ----------------
__device__ __align__(16) float  g_A[BATCH * LSEQ * HDIM];
__device__ __align__(16) float  g_C[BATCH * LSEQ * HDIM];
__device__ __align__(16) __half g_W1h[2 * KPAD * KPAD];
__device__ __align__(16) float  g_T2[11 * HDIM];

// ---------------- packed f32x2 helpers ----------------
__device__ __forceinline__ uint64_t f2pk(float lo, float hi) {
    uint64_t r; asm("mov.b64 %0,{%1,%2};" : "=l"(r) : "f"(lo), "f"(hi)); return r;
}
__device__ __forceinline__ void f2up(uint64_t v, float& lo, float& hi) {
    asm("mov.b64 {%0,%1},%2;" : "=f"(lo), "=f"(hi) : "l"(v));
}
__device__ __forceinline__ uint64_t addx2(uint64_t a, uint64_t b) {
    uint64_t r; asm("add.rn.f32x2 %0,%1,%2;" : "=l"(r) : "l"(a), "l"(b)); return r;
}
__device__ __forceinline__ uint64_t fmax2(uint64_t a, uint64_t b, uint64_t c) {
    uint64_t r; asm("fma.rn.f32x2 %0,%1,%2,%3;" : "=l"(r) : "l"(a), "l"(b), "l"(c)); return r;
}
__device__ __forceinline__ unsigned pkh2(float a, float b) {
    __half2 h = __floats2half2_rn(a, b);
    return *reinterpret_cast<unsigned*>(&h);
}

// ---------------- prep v3: ONLY W1h staging + T2 table (113 blocks) ----------------
__global__ __launch_bounds__(256) void prep_kernel(
    const float* __restrict__ posW, const float* __restrict__ W1,
    const float* __restrict__ b1)
{
    const int bid = blockIdx.x;
    const int tid = threadIdx.x;

    if (bid < 100) {
        const int task = bid * 256 + tid;        // 0..25599
        const int z = task / 12800;
        const int rem = task - z * 12800;
        const int n = rem / 40;
        const int ck = rem - n * 40;
        unsigned h[4] = {0u, 0u, 0u, 0u};
        if (n < HDIM && ck <= 37) {
            const float* src = W1 + n * W1COLS + z * 300 + ck * 8;
            float v[8];
#pragma unroll
            for (int e = 0; e < 8; e++) {
                int k = ck * 8 + e;
                v[e] = (k < HDIM) ? src[e] : 0.f;
            }
            h[0] = pkh2(v[0], v[1]); h[1] = pkh2(v[2], v[3]);
            h[2] = pkh2(v[4], v[5]); h[3] = pkh2(v[6], v[7]);
        }
        *(uint4*)&g_W1h[(z * KPAD + n) * KPAD + ck * 8] =
            make_uint4(h[0], h[1], h[2], h[3]);
    } else {
        const int gid = (bid - 100) * 256 + tid;
        if (gid < 11 * HDIM) {
            int r = gid / HDIM;
            int hh = gid - r * HDIM;
            float w[11];
#pragma unroll
            for (int rp = 0; rp < 11; rp++) {
                float d = (float)(r - rp);
                int aa = rp - 5; if (aa < 0) aa = -aa;
                w[rp] = (float)(LSEQ - aa) * expf(-d * d);
            }
            float acc = b1[hh];
            const float* w1row = W1 + hh * W1COLS + 600;
#pragma unroll 2
            for (int d = 0; d < 50; d++) {
                float tv = 0.f;
#pragma unroll
                for (int rp = 0; rp < 11; rp++) tv += w[rp] * posW[rp * 50 + d];
                acc += tv * w1row[d];
            }
            g_T2[gid] = acc;
        }
    }
}

// ---------------- GEMM: A fused fp32->fp16 (LDG+cvt+STS, 2-buf), B cp.async fp16 ----
#define GBM 128
#define GBN 64
#define GBK 32
#define KSTRH 40
#define NIT 10
#define NSTG 3

__device__ __forceinline__ void cp_async16(uint32_t dst, const void* src) {
    asm volatile("cp.async.cg.shared.global [%0], [%1], 16;\n"
                 :: "r"(dst), "l"(src));
}

__global__ __launch_bounds__(256) void gemm_f16_kernel(
    const float* __restrict__ h_e, const float* __restrict__ h_c,
    const float* __restrict__ h_share)
{
    __shared__ __align__(16) __half As[2][GBM][KSTRH];     // 20480 B
    __shared__ __align__(16) __half Bs[NSTG][GBN][KSTRH];  // 15360 B

    const int z = blockIdx.z;
    const float* Xe = z ? h_c : h_e;
    const __half* Wz = g_W1h + z * KPAD * KPAD;
    float* Out = z ? g_C : g_A;

    const int m0 = blockIdx.y * GBM;
    const int n0 = blockIdx.x * GBN;
    const int tid = threadIdx.x;
    const int warp = tid >> 5;
    const int lane = tid & 31;
    const int wm = (warp & 3) * 32;
    const int wn = (warp >> 2) * 32;
    const int lq = lane >> 2;
    const int lr = lane & 3;

    const int arow = tid >> 2;        // 0..63 (+64 second row)
    const int ac   = (tid & 3) * 8;   // k offset within 32-k tile
    const int brow = tid >> 2;
    const int bc   = (tid & 3) * 8;

    const float* eSrc = Xe + (m0 + arow) * HDIM + ac;
    const float* sSrc = h_share + (m0 + arow) * HDIM + ac;
    const __half* bSrc = Wz + (n0 + brow) * KPAD + bc;

    const uint32_t bD0 = (uint32_t)__cvta_generic_to_shared(&Bs[0][brow][bc]);
    const uint32_t bBufSz = GBN * KSTRH * 2;

    float4 ae[2][2], as_[2][2];
    const float4 zero4 = make_float4(0.f, 0.f, 0.f, 0.f);

    auto ldA = [&](int k0) {
        const bool v0 = (k0 + ac) < HDIM;
        const bool v1 = (k0 + ac + 4) < HDIM;
#pragma unroll
        for (int r = 0; r < 2; r++) {
            const float* pe = eSrc + r * 64 * HDIM + k0;
            const float* ps = sSrc + r * 64 * HDIM + k0;
            ae[r][0] = v0 ? *(const float4*)pe : zero4;
            ae[r][1] = v1 ? *(const float4*)(pe + 4) : zero4;
            as_[r][0] = v0 ? *(const float4*)ps : zero4;
            as_[r][1] = v1 ? *(const float4*)(ps + 4) : zero4;
        }
    };
    auto stsA = [&](int buf) {
#pragma unroll
        for (int r = 0; r < 2; r++) {
            float4 a0 = ae[r][0], s0 = as_[r][0];
            float4 a1 = ae[r][1], s1 = as_[r][1];
            uint4 o;
            o.x = pkh2(a0.x + s0.x, a0.y + s0.y);
            o.y = pkh2(a0.z + s0.z, a0.w + s0.w);
            o.z = pkh2(a1.x + s1.x, a1.y + s1.y);
            o.w = pkh2(a1.z + s1.z, a1.w + s1.w);
            *(uint4*)&As[buf][arow + r * 64][ac] = o;
        }
    };
    auto issueB = [&](int stage, int k0) {
        cp_async16(bD0 + stage * bBufSz, bSrc + k0);
    };

    float acc[2][4][4];
#pragma unroll
    for (int a = 0; a < 2; a++)
#pragma unroll
        for (int b = 0; b < 4; b++)
#pragma unroll
            for (int c = 0; c < 4; c++) acc[a][b][c] = 0.f;

    // prologue
    ldA(0);
    stsA(0);
    issueB(0, 0);
    asm volatile("cp.async.commit_group;\n" ::: "memory");
    issueB(1, GBK);
    asm volatile("cp.async.commit_group;\n" ::: "memory");

    int buf = 0;   // B stage index
    for (int it = 0; it < NIT; it++) {
        asm volatile("cp.async.wait_group 1;\n" ::: "memory");
        __syncthreads();   // publish As[it&1] (STS'd last iter / prologue) + Bs

        if (it + 1 < NIT) ldA((it + 1) * GBK);     // long-latency LDGs in flight

        int nx = it + 2;
        if (nx < NIT) issueB(nx % NSTG, nx * GBK);
        asm volatile("cp.async.commit_group;\n" ::: "memory");

        const int abuf = it & 1;
#pragma unroll
        for (int ks = 0; ks < 2; ks++) {
            const int kh = ks * 16 + lr * 2;
            unsigned af[2][4];
#pragma unroll
            for (int mf = 0; mf < 2; mf++) {
                const int mrow = wm + mf * 16 + lq;
                af[mf][0] = *(const unsigned*)&As[abuf][mrow][kh];
                af[mf][1] = *(const unsigned*)&As[abuf][mrow + 8][kh];
                af[mf][2] = *(const unsigned*)&As[abuf][mrow][kh + 8];
                af[mf][3] = *(const unsigned*)&As[abuf][mrow + 8][kh + 8];
            }
            unsigned bf[4][2];
#pragma unroll
            for (int nf = 0; nf < 4; nf++) {
                const int nrow = wn + nf * 8 + lq;
                bf[nf][0] = *(const unsigned*)&Bs[buf][nrow][kh];
                bf[nf][1] = *(const unsigned*)&Bs[buf][nrow][kh + 8];
            }
#pragma unroll
            for (int mf = 0; mf < 2; mf++)
#pragma unroll
                for (int nf = 0; nf < 4; nf++) {
                    asm volatile(
                        "mma.sync.aligned.m16n8k16.row.col.f32.f16.f16.f32 "
                        "{%0,%1,%2,%3}, {%4,%5,%6,%7}, {%8,%9}, {%0,%1,%2,%3};\n"
                        : "+f"(acc[mf][nf][0]), "+f"(acc[mf][nf][1]),
                          "+f"(acc[mf][nf][2]), "+f"(acc[mf][nf][3])
                        : "r"(af[mf][0]), "r"(af[mf][1]), "r"(af[mf][2]), "r"(af[mf][3]),
                          "r"(bf[nf][0]), "r"(bf[nf][1]));
                }
        }

        if (it + 1 < NIT) stsA((it + 1) & 1);   // buffer freed by the sync above
        buf = (buf + 1 == NSTG) ? 0 : buf + 1;
    }

#pragma unroll
    for (int mf = 0; mf < 2; mf++) {
        const int row = m0 + wm + mf * 16 + lq;
#pragma unroll
        for (int nf = 0; nf < 4; nf++) {
            const int col = n0 + wn + nf * 8 + 2 * lr;
            if (col < HDIM) {
                *(float2*)&Out[row * HDIM + col] =
                    make_float2(acc[mf][nf][0], acc[mf][nf][1]);
                *(float2*)&Out[(row + 8) * HDIM + col] =
                    make_float2(acc[mf][nf][2], acc[mf][nf][3]);
            }
        }
    }
}

// ---------------- epilogue v5 (R12 known-good, byte-identical) ----------------
#define CHI 8

__device__ __forceinline__ int band_off(int i) {
    if (i <= 1019) return (i < 5) ? (i * i + 11 * i) / 2 : 11 * i - 15;
    int s = i - 1019;
    return 11194 + 10 * s - s * (s - 1) / 2;
}

__global__ __launch_bounds__(256) void epi_kernel(
    const float* __restrict__ lng, const float* __restrict__ lnb,
    const float* __restrict__ W2, const float* __restrict__ b2,
    float* __restrict__ out, int write_pos)
{
    __shared__ __align__(16) float s_g[304];
    __shared__ __align__(16) float s_b[304];
    __shared__ __align__(16) float s_w[304];
    __shared__ __align__(16) float sT2[11 * HDIM];
    __shared__ __align__(16) float sA[CHI * HDIM];
    __shared__ __align__(16) float sC[(CHI + 10) * HDIM];

    const int tid = threadIdx.x;
    const int i0 = blockIdx.x * CHI;
    const int b = blockIdx.y;

    for (int h = tid; h < HDIM; h += 256) {
        s_g[h] = lng[h]; s_b[h] = lnb[h]; s_w[h] = W2[h];
    }
    for (int q = tid; q < 11 * HDIM / 4; q += 256)
        ((float4*)sT2)[q] = ((const float4*)g_T2)[q];
    {
        const float4* src = (const float4*)(g_A + (b * LSEQ + i0) * HDIM);
        float4* dst = (float4*)sA;
        for (int q = tid; q < CHI * (HDIM / 4); q += 256) dst[q] = src[q];
    }
    const int j0c = (i0 - 5 < 0) ? 0 : i0 - 5;
    const int j1c = (i0 + CHI + 4 > LSEQ - 1) ? LSEQ - 1 : i0 + CHI + 4;
    const int ncr = j1c - j0c + 1;
    {
        const float4* src = (const float4*)(g_C + (b * LSEQ + j0c) * HDIM);
        float4* dst = (float4*)sC;
        for (int q = tid; q < ncr * (HDIM / 4); q += 256) dst[q] = src[q];
    }
    __syncthreads();

    const int warp = tid >> 5;
    const int lane = tid & 31;
    const int half = lane >> 4;
    const int l16 = lane & 15;
    const float bias = __ldg(b2);
    const float inv = 1.f / (float)HDIM;

    for (int it = 0; it < 6; it++) {
        int p = it * 16 + warp * 2 + half;
        bool pv = (p < 88);
        int pc = pv ? p : 0;
        int i_off = pc / 11;
        int rel = pc - i_off * 11 - 5;
        int i = i0 + i_off;
        int j = i + rel;
        pv = pv && (j >= 0) && (j < LSEQ);

        const ulonglong2* a4 = (const ulonglong2*)(sA + i_off * HDIM);
        const ulonglong2* c4 = (const ulonglong2*)(sC + (pv ? (j - j0c) : 0) * HDIM);
        const ulonglong2* t4 = (const ulonglong2*)(sT2 + (rel + 5) * HDIM);

        ulonglong2 v[5];
        uint64_t s1p = 0ull, s2p = 0ull;
#pragma unroll
        for (int q = 0; q < 5; q++) {
            int f = q * 16 + l16;
            if (f < 75) {
                ulonglong2 a = a4[f], c = c4[f], t = t4[f];
                uint64_t x0 = addx2(addx2(a.x, c.x), t.x);
                uint64_t x1 = addx2(addx2(a.y, c.y), t.y);
                v[q].x = x0; v[q].y = x1;
                s1p = addx2(s1p, addx2(x0, x1));
                s2p = fmax2(x0, x0, s2p);
                s2p = fmax2(x1, x1, s2p);
            } else {
                v[q].x = 0ull; v[q].y = 0ull;
            }
        }
        float s1a, s1b, s2a, s2b;
        f2up(s1p, s1a, s1b); f2up(s2p, s2a, s2b);
        float s1 = s1a + s1b, s2 = s2a + s2b;
#pragma unroll
        for (int o = 8; o; o >>= 1) {
            s1 += __shfl_xor_sync(0xffffffffu, s1, o);
            s2 += __shfl_xor_sync(0xffffffffu, s2, o);
        }
        float mu = s1 * inv;
        float var = s2 * inv - mu * mu;
        float rstd = rsqrtf(var + 1e-5f);
        uint64_t rp = f2pk(rstd, rstd);
        uint64_t mp = f2pk(-mu * rstd, -mu * rstd);

        float dot = 0.f;
#pragma unroll
        for (int q = 0; q < 5; q++) {
            int f = q * 16 + l16;
            if (f < 75) {
                ulonglong2 g = ((const ulonglong2*)s_g)[f];
                ulonglong2 bb = ((const ulonglong2*)s_b)[f];
                float4 w = ((const float4*)s_w)[f];
                uint64_t u0 = fmax2(v[q].x, rp, mp);
                uint64_t u1 = fmax2(v[q].y, rp, mp);
                uint64_t y0 = fmax2(u0, g.x, bb.x);
                uint64_t y1 = fmax2(u1, g.y, bb.y);
                float e0, e1, e2, e3;
                f2up(y0, e0, e1); f2up(y1, e2, e3);
                e0 = (e0 > 0.f) ? e0 : (__expf(e0) - 1.f);
                e1 = (e1 > 0.f) ? e1 : (__expf(e1) - 1.f);
                e2 = (e2 > 0.f) ? e2 : (__expf(e2) - 1.f);
                e3 = (e3 > 0.f) ? e3 : (__expf(e3) - 1.f);
                dot += e0 * w.x + e1 * w.y + e2 * w.z + e3 * w.w;
            }
        }
#pragma unroll
        for (int o = 8; o; o >>= 1) dot += __shfl_xor_sync(0xffffffffu, dot, o);

        if (pv && l16 == 0) {
            int jlo = (i - 5 < 0) ? 0 : i - 5;
            int oidx = band_off(i) + (j - jlo);
            out[b * NC + oidx] = dot + bias;
            if (write_pos && b == 0) {
                out[NPAIR + 2 * oidx]     = (float)(i + 1);
                out[NPAIR + 2 * oidx + 1] = (float)(j + 1);
            }
        }
    }
}

// ---------------- launcher ----------------
extern "C" void kernel_launch(void* const* d_in, const int* in_sizes, int n_in,
                              void* d_out, int out_size) {
    const float* h_e     = (const float*)d_in[0];
    const float* h_c     = (const float*)d_in[1];
    const float* h_share = (const float*)d_in[2];
    const float* pos_W   = (const float*)d_in[4];
    const float* W1      = (const float*)d_in[5];
    const float* b1      = (const float*)d_in[6];
    const float* ln_g    = (const float*)d_in[7];
    const float* ln_b    = (const float*)d_in[8];
    const float* W2      = (const float*)d_in[9];
    const float* b2      = (const float*)d_in[10];
    float* out = (float*)d_out;

    prep_kernel<<<113, 256>>>(pos_W, W1, b1);

    dim3 ggrid((HDIM + GBN - 1) / GBN, (BATCH * LSEQ) / GBM, 2);
    gemm_f16_kernel<<<ggrid, 256>>>(h_e, h_c, h_share);

    int write_pos = (out_size >= NPAIR + 2 * NC) ? 1 : 0;
    dim3 egrid(LSEQ / CHI, BATCH);
    epi_kernel<<<egrid, 256>>>(ln_g, ln_b, W2, b2, out, write_pos);
}

// round 17
// speedup vs baseline: 1.4090x; 1.4090x over previous
#include <cuda_runtime.h>
#include <cuda_fp16.h>
#include <math.h>
#include <stdint.h>

#define LSEQ 1024
#define BATCH 8
#define HDIM 300
#define NC 11234
#define W1COLS 650
#define NPAIR (BATCH * NC)
#define KPAD 320

// ---------------- device scratch ----------------
__device__ __align__(16) float  g_A[BATCH * LSEQ * HDIM];
__device__ __align__(16) float  g_C[BATCH * LSEQ * HDIM];
__device__ __align__(16) __half g_He[BATCH * LSEQ * KPAD];
__device__ __align__(16) __half g_Hc[BATCH * LSEQ * KPAD];
__device__ __align__(16) __half g_W1h[2 * KPAD * KPAD];
__device__ __align__(16) float  g_T2[11 * HDIM];

// ---------------- packed f32x2 helpers ----------------
__device__ __forceinline__ uint64_t f2pk(float lo, float hi) {
    uint64_t r; asm("mov.b64 %0,{%1,%2};" : "=l"(r) : "f"(lo), "f"(hi)); return r;
}
__device__ __forceinline__ void f2up(uint64_t v, float& lo, float& hi) {
    asm("mov.b64 {%0,%1},%2;" : "=f"(lo), "=f"(hi) : "l"(v));
}
__device__ __forceinline__ uint64_t addx2(uint64_t a, uint64_t b) {
    uint64_t r; asm("add.rn.f32x2 %0,%1,%2;" : "=l"(r) : "l"(a), "l"(b)); return r;
}
__device__ __forceinline__ uint64_t fmax2(uint64_t a, uint64_t b, uint64_t c) {
    uint64_t r; asm("fma.rn.f32x2 %0,%1,%2,%3;" : "=l"(r) : "l"(a), "l"(b), "l"(c)); return r;
}
__device__ __forceinline__ unsigned pkh2(float a, float b) {
    __half2 h = __floats2half2_rn(a, b);
    return *reinterpret_cast<unsigned*>(&h);
}
__device__ __forceinline__ void cp_async16p(uint32_t dst, const void* src) {
    asm volatile("cp.async.cg.shared.global [%0], [%1], 16;\n"
                 :: "r"(dst), "l"(src));
}

// ---------------- prep v4 ----------------
// bid 0..10:    T2 (one rel per block, smem-staged coalesced)
// bid 11..110:  W1h staging (as R12)
// bid 111..366: He/Hc copy via cp.async pipeline (32 rows per block)
#define CPROWS 32
#define CHROWS 4

__global__ __launch_bounds__(256) void prep_kernel(
    const float* __restrict__ h_e, const float* __restrict__ h_c,
    const float* __restrict__ h_share,
    const float* __restrict__ posW, const float* __restrict__ W1,
    const float* __restrict__ b1)
{
    __shared__ __align__(16) char smraw[28800];
    const int bid = blockIdx.x;
    const int tid = threadIdx.x;

    if (bid < 11) {
        // ---- T2: block computes row r for all 300 h, fully smem-staged ----
        const int r = bid;
        float* sPW = (float*)smraw;            // 550
        float* sM  = sPW + 560;                // 50
        float* sW  = sM + 56;                  // 100*53 = 5300 -> total ~23.7KB
        for (int q = tid; q < 550; q += 256) sPW[q] = posW[q];
        __syncthreads();
        if (tid < 50) {
            float acc = 0.f;
#pragma unroll
            for (int rp = 0; rp < 11; rp++) {
                float d = (float)(r - rp);
                int aa = rp - 5; if (aa < 0) aa = -aa;
                acc += (float)(LSEQ - aa) * expf(-d * d) * sPW[rp * 50 + tid];
            }
            sM[tid] = acc;
        }
        __syncthreads();
#pragma unroll
        for (int h0 = 0; h0 < 300; h0 += 100) {
            // stage W1[h0..h0+100)[600..650) coalesced
            for (int idx = tid; idx < 100 * 50; idx += 256) {
                int row = idx / 50, d = idx - row * 50;
                sW[row * 53 + d] = W1[(h0 + row) * W1COLS + 600 + d];
            }
            __syncthreads();
            if (tid < 100) {
                float acc = b1[h0 + tid];
                const float* wr = sW + tid * 53;
#pragma unroll 10
                for (int d = 0; d < 50; d++) acc += sM[d] * wr[d];
                g_T2[r * HDIM + h0 + tid] = acc;
            }
            __syncthreads();
        }
        return;
    }

    if (bid < 111) {
        // ---- W1h staging (R12 pattern) ----
        const int task = (bid - 11) * 256 + tid;   // 0..25599
        const int z = task / 12800;
        const int rem = task - z * 12800;
        const int n = rem / 40;
        const int ck = rem - n * 40;
        unsigned h[4] = {0u, 0u, 0u, 0u};
        if (n < HDIM && ck <= 37) {
            const float* src = W1 + n * W1COLS + z * 300 + ck * 8;
            float v[8];
#pragma unroll
            for (int e = 0; e < 8; e++) {
                int k = ck * 8 + e;
                v[e] = (k < HDIM) ? src[e] : 0.f;
            }
            h[0] = pkh2(v[0], v[1]); h[1] = pkh2(v[2], v[3]);
            h[2] = pkh2(v[4], v[5]); h[3] = pkh2(v[6], v[7]);
        }
        *(uint4*)&g_W1h[(z * KPAD + n) * KPAD + ck * 8] =
            make_uint4(h[0], h[1], h[2], h[3]);
        return;
    }

    // ---- He/Hc copy: cp.async pipelined, 32 rows/block, 8 chunks of 4 rows ----
    float (*sbuf)[3][CHROWS][300] = (float (*)[3][CHROWS][300])smraw; // 28800 B
    const int row0 = (bid - 111) * CPROWS;
    const float* bases[3] = {h_e, h_c, h_share};

    auto loadChunk = [&](int ch, int st) {
        for (int q = tid; q < 900; q += 256) {
            int a = q / 300, rem = q - a * 300;
            int rl = rem / 75, off = rem - rl * 75;
            const float* src = bases[a] + (row0 + ch * CHROWS + rl) * HDIM + off * 4;
            uint32_t dst = (uint32_t)__cvta_generic_to_shared(&sbuf[st][a][rl][off * 4]);
            cp_async16p(dst, src);
        }
    };

    loadChunk(0, 0);
    asm volatile("cp.async.commit_group;\n" ::: "memory");

    for (int ch = 0; ch < 8; ch++) {
        if (ch + 1 < 8) loadChunk(ch + 1, (ch + 1) & 1);
        asm volatile("cp.async.commit_group;\n" ::: "memory");
        asm volatile("cp.async.wait_group 1;\n" ::: "memory");
        __syncthreads();

        const int st = ch & 1;
        for (int q = tid; q < 320; q += 256) {
            int a = q / 160, rem = q - a * 160;
            int rl = rem / 40, ck = rem - rl * 40;
            uint4 o = make_uint4(0, 0, 0, 0);
            if (ck <= 37) {
                const float* ps = &sbuf[st][2][rl][ck * 8];
                const float* px = &sbuf[st][a][rl][ck * 8];
                float4 x0 = *(const float4*)px;
                float4 s0 = *(const float4*)ps;
                float4 x1 = make_float4(0.f, 0.f, 0.f, 0.f), s1 = x1;
                if (ck <= 36) {
                    x1 = *(const float4*)(px + 4);
                    s1 = *(const float4*)(ps + 4);
                }
                o.x = pkh2(x0.x + s0.x, x0.y + s0.y);
                o.y = pkh2(x0.z + s0.z, x0.w + s0.w);
                o.z = pkh2(x1.x + s1.x, x1.y + s1.y);
                o.w = pkh2(x1.z + s1.z, x1.w + s1.w);
            }
            __half* Out = a ? g_Hc : g_He;
            *(uint4*)&Out[(row0 + ch * CHROWS + rl) * KPAD + ck * 8] = o;
        }
        __syncthreads();   // buffer st reusable for load(ch+2)
    }
}

// ---------------- fp16 GEMM (R12 known-good, byte-identical) ----------------
#define GBM 128
#define GBN 64
#define GBK 32
#define KSTRH 40
#define NIT 10
#define NSTG 3

__global__ __launch_bounds__(256) void gemm_f16_kernel()
{
    __shared__ __align__(16) __half As[NSTG][GBM][KSTRH];
    __shared__ __align__(16) __half Bs[NSTG][GBN][KSTRH];

    const int z = blockIdx.z;
    const __half* X = z ? g_Hc : g_He;
    const __half* Wz = g_W1h + z * KPAD * KPAD;
    float* Out = z ? g_C : g_A;

    const int m0 = blockIdx.y * GBM;
    const int n0 = blockIdx.x * GBN;
    const int tid = threadIdx.x;
    const int warp = tid >> 5;
    const int lane = tid & 31;
    const int wm = (warp & 3) * 32;
    const int wn = (warp >> 2) * 32;
    const int lq = lane >> 2;
    const int lr = lane & 3;

    const int arow = tid >> 2;
    const int ac   = (tid & 3) * 8;
    const int brow = tid >> 2;
    const int bc   = (tid & 3) * 8;

    const __half* aSrc0 = X + (m0 + arow) * KPAD + ac;
    const __half* aSrc1 = X + (m0 + arow + 64) * KPAD + ac;
    const __half* bSrc0 = Wz + (n0 + brow) * KPAD + bc;

    const uint32_t aD0 = (uint32_t)__cvta_generic_to_shared(&As[0][arow][ac]);
    const uint32_t aD1 = (uint32_t)__cvta_generic_to_shared(&As[0][arow + 64][ac]);
    const uint32_t bD0 = (uint32_t)__cvta_generic_to_shared(&Bs[0][brow][bc]);
    const uint32_t aBufSz = GBM * KSTRH * 2;
    const uint32_t bBufSz = GBN * KSTRH * 2;

    float acc[2][4][4];
#pragma unroll
    for (int a = 0; a < 2; a++)
#pragma unroll
        for (int b = 0; b < 4; b++)
#pragma unroll
            for (int c = 0; c < 4; c++) acc[a][b][c] = 0.f;

    auto issue = [&](int stage, int k0) {
        cp_async16p(aD0 + stage * aBufSz, aSrc0 + k0);
        cp_async16p(aD1 + stage * aBufSz, aSrc1 + k0);
        cp_async16p(bD0 + stage * bBufSz, bSrc0 + k0);
    };

    issue(0, 0);
    asm volatile("cp.async.commit_group;\n" ::: "memory");
    issue(1, GBK);
    asm volatile("cp.async.commit_group;\n" ::: "memory");

    int buf = 0;
    for (int it = 0; it < NIT; it++) {
        asm volatile("cp.async.wait_group 1;\n" ::: "memory");
        __syncthreads();

        int nx = it + 2;
        if (nx < NIT) issue(nx % NSTG, nx * GBK);
        asm volatile("cp.async.commit_group;\n" ::: "memory");

#pragma unroll
        for (int ks = 0; ks < 2; ks++) {
            const int kh = ks * 16 + lr * 2;
            unsigned af[2][4];
#pragma unroll
            for (int mf = 0; mf < 2; mf++) {
                const int mrow = wm + mf * 16 + lq;
                af[mf][0] = *(const unsigned*)&As[buf][mrow][kh];
                af[mf][1] = *(const unsigned*)&As[buf][mrow + 8][kh];
                af[mf][2] = *(const unsigned*)&As[buf][mrow][kh + 8];
                af[mf][3] = *(const unsigned*)&As[buf][mrow + 8][kh + 8];
            }
            unsigned bf[4][2];
#pragma unroll
            for (int nf = 0; nf < 4; nf++) {
                const int nrow = wn + nf * 8 + lq;
                bf[nf][0] = *(const unsigned*)&Bs[buf][nrow][kh];
                bf[nf][1] = *(const unsigned*)&Bs[buf][nrow][kh + 8];
            }
#pragma unroll
            for (int mf = 0; mf < 2; mf++)
#pragma unroll
                for (int nf = 0; nf < 4; nf++) {
                    asm volatile(
                        "mma.sync.aligned.m16n8k16.row.col.f32.f16.f16.f32 "
                        "{%0,%1,%2,%3}, {%4,%5,%6,%7}, {%8,%9}, {%0,%1,%2,%3};\n"
                        : "+f"(acc[mf][nf][0]), "+f"(acc[mf][nf][1]),
                          "+f"(acc[mf][nf][2]), "+f"(acc[mf][nf][3])
                        : "r"(af[mf][0]), "r"(af[mf][1]), "r"(af[mf][2]), "r"(af[mf][3]),
                          "r"(bf[nf][0]), "r"(bf[nf][1]));
                }
        }
        buf = (buf + 1 == NSTG) ? 0 : buf + 1;
    }

#pragma unroll
    for (int mf = 0; mf < 2; mf++) {
        const int row = m0 + wm + mf * 16 + lq;
#pragma unroll
        for (int nf = 0; nf < 4; nf++) {
            const int col = n0 + wn + nf * 8 + 2 * lr;
            if (col < HDIM) {
                *(float2*)&Out[row * HDIM + col] =
                    make_float2(acc[mf][nf][0], acc[mf][nf][1]);
                *(float2*)&Out[(row + 8) * HDIM + col] =
                    make_float2(acc[mf][nf][2], acc[mf][nf][3]);
            }
        }
    }
}

// ---------------- epilogue v5 (R12 known-good, byte-identical) ----------------
#define CHI 8

__device__ __forceinline__ int band_off(int i) {
    if (i <= 1019) return (i < 5) ? (i * i + 11 * i) / 2 : 11 * i - 15;
    int s = i - 1019;
    return 11194 + 10 * s - s * (s - 1) / 2;
}

__global__ __launch_bounds__(256) void epi_kernel(
    const float* __restrict__ lng, const float* __restrict__ lnb,
    const float* __restrict__ W2, const float* __restrict__ b2,
    float* __restrict__ out, int write_pos)
{
    __shared__ __align__(16) float s_g[304];
    __shared__ __align__(16) float s_b[304];
    __shared__ __align__(16) float s_w[304];
    __shared__ __align__(16) float sT2[11 * HDIM];
    __shared__ __align__(16) float sA[CHI * HDIM];
    __shared__ __align__(16) float sC[(CHI + 10) * HDIM];

    const int tid = threadIdx.x;
    const int i0 = blockIdx.x * CHI;
    const int b = blockIdx.y;

    for (int h = tid; h < HDIM; h += 256) {
        s_g[h] = lng[h]; s_b[h] = lnb[h]; s_w[h] = W2[h];
    }
    for (int q = tid; q < 11 * HDIM / 4; q += 256)
        ((float4*)sT2)[q] = ((const float4*)g_T2)[q];
    {
        const float4* src = (const float4*)(g_A + (b * LSEQ + i0) * HDIM);
        float4* dst = (float4*)sA;
        for (int q = tid; q < CHI * (HDIM / 4); q += 256) dst[q] = src[q];
    }
    const int j0c = (i0 - 5 < 0) ? 0 : i0 - 5;
    const int j1c = (i0 + CHI + 4 > LSEQ - 1) ? LSEQ - 1 : i0 + CHI + 4;
    const int ncr = j1c - j0c + 1;
    {
        const float4* src = (const float4*)(g_C + (b * LSEQ + j0c) * HDIM);
        float4* dst = (float4*)sC;
        for (int q = tid; q < ncr * (HDIM / 4); q += 256) dst[q] = src[q];
    }
    __syncthreads();

    const int warp = tid >> 5;
    const int lane = tid & 31;
    const int half = lane >> 4;
    const int l16 = lane & 15;
    const float bias = __ldg(b2);
    const float inv = 1.f / (float)HDIM;

    for (int it = 0; it < 6; it++) {
        int p = it * 16 + warp * 2 + half;
        bool pv = (p < 88);
        int pc = pv ? p : 0;
        int i_off = pc / 11;
        int rel = pc - i_off * 11 - 5;
        int i = i0 + i_off;
        int j = i + rel;
        pv = pv && (j >= 0) && (j < LSEQ);

        const ulonglong2* a4 = (const ulonglong2*)(sA + i_off * HDIM);
        const ulonglong2* c4 = (const ulonglong2*)(sC + (pv ? (j - j0c) : 0) * HDIM);
        const ulonglong2* t4 = (const ulonglong2*)(sT2 + (rel + 5) * HDIM);

        ulonglong2 v[5];
        uint64_t s1p = 0ull, s2p = 0ull;
#pragma unroll
        for (int q = 0; q < 5; q++) {
            int f = q * 16 + l16;
            if (f < 75) {
                ulonglong2 a = a4[f], c = c4[f], t = t4[f];
                uint64_t x0 = addx2(addx2(a.x, c.x), t.x);
                uint64_t x1 = addx2(addx2(a.y, c.y), t.y);
                v[q].x = x0; v[q].y = x1;
                s1p = addx2(s1p, addx2(x0, x1));
                s2p = fmax2(x0, x0, s2p);
                s2p = fmax2(x1, x1, s2p);
            } else {
                v[q].x = 0ull; v[q].y = 0ull;
            }
        }
        float s1a, s1b, s2a, s2b;
        f2up(s1p, s1a, s1b); f2up(s2p, s2a, s2b);
        float s1 = s1a + s1b, s2 = s2a + s2b;
#pragma unroll
        for (int o = 8; o; o >>= 1) {
            s1 += __shfl_xor_sync(0xffffffffu, s1, o);
            s2 += __shfl_xor_sync(0xffffffffu, s2, o);
        }
        float mu = s1 * inv;
        float var = s2 * inv - mu * mu;
        float rstd = rsqrtf(var + 1e-5f);
        uint64_t rp = f2pk(rstd, rstd);
        uint64_t mp = f2pk(-mu * rstd, -mu * rstd);

        float dot = 0.f;
#pragma unroll
        for (int q = 0; q < 5; q++) {
            int f = q * 16 + l16;
            if (f < 75) {
                ulonglong2 g = ((const ulonglong2*)s_g)[f];
                ulonglong2 bb = ((const ulonglong2*)s_b)[f];
                float4 w = ((const float4*)s_w)[f];
                uint64_t u0 = fmax2(v[q].x, rp, mp);
                uint64_t u1 = fmax2(v[q].y, rp, mp);
                uint64_t y0 = fmax2(u0, g.x, bb.x);
                uint64_t y1 = fmax2(u1, g.y, bb.y);
                float e0, e1, e2, e3;
                f2up(y0, e0, e1); f2up(y1, e2, e3);
                e0 = (e0 > 0.f) ? e0 : (__expf(e0) - 1.f);
                e1 = (e1 > 0.f) ? e1 : (__expf(e1) - 1.f);
                e2 = (e2 > 0.f) ? e2 : (__expf(e2) - 1.f);
                e3 = (e3 > 0.f) ? e3 : (__expf(e3) - 1.f);
                dot += e0 * w.x + e1 * w.y + e2 * w.z + e3 * w.w;
            }
        }
#pragma unroll
        for (int o = 8; o; o >>= 1) dot += __shfl_xor_sync(0xffffffffu, dot, o);

        if (pv && l16 == 0) {
            int jlo = (i - 5 < 0) ? 0 : i - 5;
            int oidx = band_off(i) + (j - jlo);
            out[b * NC + oidx] = dot + bias;
            if (write_pos && b == 0) {
                out[NPAIR + 2 * oidx]     = (float)(i + 1);
                out[NPAIR + 2 * oidx + 1] = (float)(j + 1);
            }
        }
    }
}

// ---------------- launcher ----------------
extern "C" void kernel_launch(void* const* d_in, const int* in_sizes, int n_in,
                              void* d_out, int out_size) {
    const float* h_e     = (const float*)d_in[0];
    const float* h_c     = (const float*)d_in[1];
    const float* h_share = (const float*)d_in[2];
    const float* pos_W   = (const float*)d_in[4];
    const float* W1      = (const float*)d_in[5];
    const float* b1      = (const float*)d_in[6];
    const float* ln_g    = (const float*)d_in[7];
    const float* ln_b    = (const float*)d_in[8];
    const float* W2      = (const float*)d_in[9];
    const float* b2      = (const float*)d_in[10];
    float* out = (float*)d_out;

    prep_kernel<<<367, 256>>>(h_e, h_c, h_share, pos_W, W1, b1);

    dim3 ggrid((HDIM + GBN - 1) / GBN, (BATCH * LSEQ) / GBM, 2);
    gemm_f16_kernel<<<ggrid, 256>>>();

    int write_pos = (out_size >= NPAIR + 2 * NC) ? 1 : 0;
    dim3 egrid(LSEQ / CHI, BATCH);
    epi_kernel<<<egrid, 256>>>(ln_g, ln_b, W2, b2, out, write_pos);
}